// round 12
// baseline (speedup 1.0000x reference)
#include <cuda_runtime.h>
#include <math.h>
#include <stdint.h>

#define B      128
#define L      196
#define DTOP   64
#define DLOW   128
#define NE     512
#define NBOOK  15
#define EPSF   1e-8f
#define INV512 (1.0f/512.0f)

#define BM        32
#define KT        8
#define KDIM      64
#define XST       34          // float2 stride per k-row (even -> 16B alignment)
#define NTHREADS  256
#define ROWBLOCKS 7

#define QUANT_OFF 0ll
#define QUANT_CNT (4ll*B*L*DLOW)
#define DIFF_OFF  (QUANT_OFF + QUANT_CNT)
#define ID_OFF    (DIFF_OFF + 1)
#define ID_CNT    (4ll*B*L)
#define OT_OFF    (ID_OFF + ID_CNT)

__device__ int   g_ind4[B*L];
__device__ float g_e2_top[NBOOK*NE];
__device__ float g_e2_lvl[4*NBOOK*NE];
__device__ float g_inve0[NBOOK*NE];
__device__ float g_embT_lvl[4*NBOOK*NE*DLOW];
__device__ float g_C[60ull*NE*NE];   // 60 books x 512 codes x 512 cols

__device__ __forceinline__ unsigned smem_u32(const void* p) {
    unsigned r;
    asm("{.reg .u64 t; cvta.to.shared.u64 t, %1; cvt.u32.u64 %0, t;}" : "=r"(r) : "l"(p));
    return r;
}
__device__ __forceinline__ void cp16(unsigned dst, const void* src) {
    asm volatile("cp.async.cg.shared.global [%0], [%1], 16;" :: "r"(dst), "l"(src));
}
#define CP_COMMIT() asm volatile("cp.async.commit_group;" ::: "memory")
#define CP_WAIT0()  asm volatile("cp.async.wait_group 0;" ::: "memory")
#define CP_WAIT1()  asm volatile("cp.async.wait_group 1;" ::: "memory")
#define FMA2(a,x,e) asm("fma.rn.f32x2 %0, %1, %2, %0;" : "+l"(a) : "l"(x), "l"(e))

__global__ void norms_kernel(const float* __restrict__ cb_top,
                             const float* __restrict__ cb_lvl,
                             float* __restrict__ out)
{
    int k = threadIdx.x, book = blockIdx.x;
    if (book == 0 && k == 0) out[DIFF_OFF] = 0.0f;
    if (book < NBOOK) {
        const float* e = cb_top + (size_t)book * DTOP * NE;
        float s = 0.f;
        #pragma unroll 8
        for (int i = 0; i < DTOP; ++i) { float v = e[(size_t)i*NE + k]; s += v*v; }
        g_e2_top[book*NE + k] = s;
    } else {
        int bl = book - NBOOK;
        const float* e = cb_lvl + (size_t)bl * DLOW * NE;
        float s = 0.f;
        #pragma unroll 8
        for (int i = 0; i < DLOW; ++i) { float v = e[(size_t)i*NE + k]; s += v*v; }
        g_e2_lvl[bl*NE + k] = s;
        if (bl < NBOOK) g_inve0[bl*NE + k] = 1.0f / (sqrtf(s) + EPSF);
    }
}

// transpose only the 60 level books: (128, NE) -> (NE, 128)
__global__ void transpose_kernel(const float* __restrict__ cb_lvl)
{
    __shared__ float tile[32][33];
    int bl = blockIdx.z;
    int k0 = blockIdx.x * 32, d0 = blockIdx.y * 32;
    const float* src = cb_lvl + (size_t)bl * DLOW * NE;
    float* dst = g_embT_lvl + (size_t)bl * NE * DLOW;
    int tx = threadIdx.x, ty = threadIdx.y;
    #pragma unroll
    for (int dy = ty; dy < 32; dy += 8)
        tile[dy][tx] = src[(size_t)(d0 + dy) * NE + k0 + tx];
    __syncthreads();
    #pragma unroll
    for (int dy = ty; dy < 32; dy += 8)
        dst[(size_t)(k0 + dy) * DLOW + d0 + tx] = tile[tx][dy];
}

// sync-free warp-private e slices + MOV-free FMA with duplicated x pairs
#define FILL_E_IMPL(EMB, BUF, TILE)                                            \
do {                                                                           \
    const char* esrc = (const char*)((EMB) + (size_t)(TILE) * KT * NE + w*64); \
    const unsigned dstb = e_base + (unsigned)(w*2 + (BUF)) * 2048u;            \
    _Pragma("unroll")                                                          \
    for (int q = 0; q < 4; ++q) {                                              \
        int idx = lane + q*32;                                                 \
        int kk = idx >> 4, c16 = idx & 15;                                     \
        cp16(dstb + (unsigned)(kk*256 + c16*16),                               \
             esrc + (size_t)kk*2048 + (size_t)c16*16);                         \
    }                                                                          \
    CP_COMMIT();                                                               \
} while (0)

#define COMPUTE_IMPL(BUF)                                                      \
do {                                                                           \
    const char* ek = (const char*)e_s + (unsigned)(w*2 + (BUF))*2048u + co*32; \
    _Pragma("unroll")                                                          \
    for (int i = 0; i < KT; ++i) {                                             \
        ulonglong2 ea = *(const ulonglong2*)(ek + i*256);                      \
        ulonglong2 eb = *(const ulonglong2*)(ek + i*256 + 16);                 \
        ulonglong2 xA = *(const ulonglong2*)(xk + i*XST);                      \
        ulonglong2 xB = *(const ulonglong2*)(xk + i*XST + 2);                  \
        ulonglong2 xC = *(const ulonglong2*)(xk + i*XST + 4);                  \
        ulonglong2 xD = *(const ulonglong2*)(xk + i*XST + 6);                  \
        FMA2(acc[0][0], xA.x, ea.x); FMA2(acc[0][1], xA.x, ea.y);              \
        FMA2(acc[0][2], xA.x, eb.x); FMA2(acc[0][3], xA.x, eb.y);              \
        FMA2(acc[1][0], xA.y, ea.x); FMA2(acc[1][1], xA.y, ea.y);              \
        FMA2(acc[1][2], xA.y, eb.x); FMA2(acc[1][3], xA.y, eb.y);              \
        FMA2(acc[2][0], xB.x, ea.x); FMA2(acc[2][1], xB.x, ea.y);              \
        FMA2(acc[2][2], xB.x, eb.x); FMA2(acc[2][3], xB.x, eb.y);              \
        FMA2(acc[3][0], xB.y, ea.x); FMA2(acc[3][1], xB.y, ea.y);              \
        FMA2(acc[3][2], xB.y, eb.x); FMA2(acc[3][3], xB.y, eb.y);              \
        FMA2(acc[4][0], xC.x, ea.x); FMA2(acc[4][1], xC.x, ea.y);              \
        FMA2(acc[4][2], xC.x, eb.x); FMA2(acc[4][3], xC.x, eb.y);              \
        FMA2(acc[5][0], xC.y, ea.x); FMA2(acc[5][1], xC.y, ea.y);              \
        FMA2(acc[5][2], xC.y, eb.x); FMA2(acc[5][3], xC.y, eb.y);              \
        FMA2(acc[6][0], xD.x, ea.x); FMA2(acc[6][1], xD.x, ea.y);              \
        FMA2(acc[6][2], xD.x, eb.x); FMA2(acc[6][3], xD.x, eb.y);              \
        FMA2(acc[7][0], xD.y, ea.x); FMA2(acc[7][1], xD.y, ea.y);              \
        FMA2(acc[7][2], xD.y, eb.x); FMA2(acc[7][3], xD.y, eb.y);              \
    }                                                                          \
    xk += KT*XST;                                                              \
} while (0)

// ---------------------------------------------------------------------------
// C table: C[book][m][n] = dot(etop[:,m], emb_lvl[book][64:128][n])
// grid(16, 60), 256 thr. x read directly from cb_top columns (coalesced).
// ---------------------------------------------------------------------------
__global__ __launch_bounds__(NTHREADS, 2)
void cpre_kernel(const float* __restrict__ cb_top,
                 const float* __restrict__ cb_lvl)
{
    __shared__ __align__(16) float  e_s[8*2*KT*64];   // 32 KB
    __shared__ __align__(16) float2 x2_s[KDIM*XST];   // 17 KB (dup pairs)

    const int mb   = blockIdx.x;
    const int book = blockIdx.y;
    const int t    = book % NBOOK;
    const int mbase = mb * BM;
    const int tid  = threadIdx.x;
    const int lane = tid & 31;
    const int w    = tid >> 5;
    const int rg8  = (lane >> 3) * 8;
    const int co   = lane & 7;
    const int colb = w * 64 + co * 8;

    const float* emb = cb_lvl + (size_t)book * DLOW * NE + (size_t)DTOP * NE;
    const unsigned e_base = smem_u32(e_s);

    unsigned long long acc[8][4];
    #pragma unroll
    for (int r = 0; r < 8; ++r)
        #pragma unroll
        for (int p = 0; p < 4; ++p) acc[r][p] = 0ull;

    FILL_E_IMPL(emb, 0, 0);
    // x rows = codes m (32), cols = d (64): read cb_top[t][c][m] (coalesced in m)
    for (int it = tid; it < BM*KDIM; it += NTHREADS) {
        int c = it >> 5, row = it & 31;
        float v = cb_top[(size_t)t*DTOP*NE + (size_t)c*NE + mbase + row];
        x2_s[c*XST + row] = make_float2(v, v);
    }
    __syncthreads();

    const unsigned long long* xk = (const unsigned long long*)x2_s + rg8;
    #pragma unroll
    for (int tt = 0; tt < KDIM/KT; ++tt) {
        if (tt + 1 < KDIM/KT) { FILL_E_IMPL(emb, (tt + 1) & 1, tt + 1); CP_WAIT1(); }
        else                  { CP_WAIT0(); }
        COMPUTE_IMPL(tt & 1);
    }

    #pragma unroll
    for (int r = 0; r < 8; ++r) {
        int m = mbase + rg8 + r;
        float gv[8];
        #pragma unroll
        for (int p = 0; p < 4; ++p)
            asm("mov.b64 {%0,%1}, %2;" : "=f"(gv[2*p]), "=f"(gv[2*p+1]) : "l"(acc[r][p]));
        float* dst = g_C + ((size_t)book*NE + m)*NE + colb;
        *(float4*)dst       = make_float4(gv[0], gv[1], gv[2], gv[3]);
        *(float4*)(dst + 4) = make_float4(gv[4], gv[5], gv[6], gv[7]);
    }
}

struct Epi {
    float minv[8][BM]; int mini[8][BM];
    float otm[8][BM], otz[8][BM], ott[8][BM];
    int ind[BM]; float dist[BM];
};

// ---------------------------------------------------------------------------
// Unified VQ kernel, K=64. Top stores g_ind4 + diff; lower adds C[ind4].
// ---------------------------------------------------------------------------
template<bool IS_TOP>
__launch_bounds__(NTHREADS, 2)
__global__ void vq_gemm(const float* __restrict__ input_list,
                        const float* __restrict__ cb_top,
                        const float* __restrict__ cb_lvl,
                        const int*   __restrict__ label,
                        float*       __restrict__ out)
{
    __shared__ __align__(16) float  e_s[8*2*KT*64];   // 32 KB (Epi aliased later)
    __shared__ __align__(16) float2 x2_s[KDIM*XST];   // 17 KB
    __shared__ int ind4s[BM];

    const int rb = blockIdx.x;
    const int b  = blockIdx.y;
    const int s  = blockIdx.z;
    const int j  = IS_TOP ? 4 : (3 - s);
    const int t  = label[b];
    const int book = j * NBOOK + t;
    const int rowbase = rb * BM;
    const int tid  = threadIdx.x;
    const int lane = tid & 31;
    const int w    = tid >> 5;
    const int rg8  = (lane >> 3) * 8;
    const int co   = lane & 7;
    const int colb = w * 64 + co * 8;

    const float* emb = IS_TOP ? (cb_top + (size_t)t * DTOP * NE)
                              : (cb_lvl + (size_t)book * DLOW * NE);
    const unsigned e_base = smem_u32(e_s);

    unsigned long long acc[8][4];
    #pragma unroll
    for (int r = 0; r < 8; ++r)
        #pragma unroll
        for (int p = 0; p < 4; ++p) acc[r][p] = 0ull;

    FILL_E_IMPL(emb, 0, 0);
    {   // stage x (coalesced LDG; 4-way STS conflict acceptable) + ind4
        const float* xin = input_list + (((size_t)j*B + b)*L)*DTOP;
        for (int it = tid; it < BM*KDIM; it += NTHREADS) {
            int row = it >> 6, c = it & 63;
            int l = rowbase + row;
            float v = (l < L) ? xin[(size_t)l*DTOP + c] : 0.f;
            x2_s[c*XST + row] = make_float2(v, v);
        }
        if (!IS_TOP && tid < BM) {
            int l = rowbase + tid;
            ind4s[tid] = (l < L) ? g_ind4[(size_t)b*L + l] : 0;
        }
    }
    __syncthreads();

    const unsigned long long* xk = (const unsigned long long*)x2_s + rg8;
    #pragma unroll
    for (int tt = 0; tt < KDIM/KT; ++tt) {
        if (tt + 1 < KDIM/KT) { FILL_E_IMPL(emb, (tt + 1) & 1, tt + 1); CP_WAIT1(); }
        else                  { CP_WAIT0(); }
        COMPUTE_IMPL(tt & 1);
    }
    __syncthreads();   // e_s dead -> alias epilogue

    Epi* ep = (Epi*)e_s;
    const float* e2p = IS_TOP ? (g_e2_top + (size_t)t * NE)
                              : (g_e2_lvl + (size_t)book * NE);
    float e2v[8];
    *(float4*)&e2v[0] = *(const float4*)&e2p[colb];
    *(float4*)&e2v[4] = *(const float4*)&e2p[colb + 4];
    const bool do_ot = (!IS_TOP) && (j == 0);
    float invev[8];
    if (do_ot) {
        const float* ip = g_inve0 + (size_t)t * NE;
        *(float4*)&invev[0] = *(const float4*)&ip[colb];
        *(float4*)&invev[4] = *(const float4*)&ip[colb + 4];
    }

    #pragma unroll
    for (int r = 0; r < 8; ++r) {
        int row = rg8 + r;
        int l = rowbase + row;

        float gv[8];
        #pragma unroll
        for (int p = 0; p < 4; ++p)
            asm("mov.b64 {%0,%1}, %2;" : "=f"(gv[2*p]), "=f"(gv[2*p+1]) : "l"(acc[r][p]));

        if (!IS_TOP) {
            const float* Cp = g_C + ((size_t)book*NE + ind4s[row])*NE + colb;
            float4 c0 = *(const float4*)Cp;
            float4 c1 = *(const float4*)(Cp + 4);
            gv[0] += c0.x; gv[1] += c0.y; gv[2] += c0.z; gv[3] += c0.w;
            gv[4] += c1.x; gv[5] += c1.y; gv[6] += c1.z; gv[7] += c1.w;
        }

        float bv = 3.4e38f; int bi = NE;
        #pragma unroll
        for (int c = 0; c < 8; ++c) {
            float v = fmaf(-2.f, gv[c], e2v[c]);
            if (v < bv || (v == bv && colb + c < bi)) { bv = v; bi = colb + c; }
        }
        #pragma unroll
        for (int o = 1; o <= 4; o <<= 1) {
            float ov = __shfl_xor_sync(0xffffffffu, bv, o);
            int   oi = __shfl_xor_sync(0xffffffffu, bi, o);
            if (ov < bv || (ov == bv && oi < bi)) { bv = ov; bi = oi; }
        }
        if (co == 0 && l < L) { ep->minv[w][row] = bv; ep->mini[w][row] = bi; }

        if (do_ot) {
            float m = -3.4e38f;
            #pragma unroll
            for (int c = 0; c < 8; ++c) m = fmaxf(m, gv[c] * INV512);
            #pragma unroll
            for (int o = 1; o <= 4; o <<= 1)
                m = fmaxf(m, __shfl_xor_sync(0xffffffffu, m, o));
            float Z = 0.f, Tt = 0.f;
            #pragma unroll
            for (int c = 0; c < 8; ++c) {
                float pe = expf(gv[c] * INV512 - m);
                Z += pe;  Tt += gv[c] * invev[c] * pe;
            }
            #pragma unroll
            for (int o = 1; o <= 4; o <<= 1) {
                Z  += __shfl_xor_sync(0xffffffffu, Z,  o);
                Tt += __shfl_xor_sync(0xffffffffu, Tt, o);
            }
            if (co == 0 && l < L) { ep->otm[w][row] = m; ep->otz[w][row] = Z; ep->ott[w][row] = Tt; }
        }
    }
    __syncthreads();

    if (tid < BM) {
        int row = tid, l = rowbase + row;
        if (l < L) {
            float s2 = 0.f;
            #pragma unroll 8
            for (int c = 0; c < KDIM; ++c) { float v = x2_s[c*XST + row].x; s2 += v*v; }
            if (!IS_TOP) s2 += g_e2_top[(size_t)t*NE + ind4s[row]];
            float bv = ep->minv[0][row]; int bi = ep->mini[0][row];
            #pragma unroll
            for (int ww = 1; ww < 8; ++ww) {
                float v = ep->minv[ww][row];
                if (v < bv) { bv = v; bi = ep->mini[ww][row]; }
            }
            ep->ind[row]  = bi;
            ep->dist[row] = s2 + bv;
            if (IS_TOP)
                g_ind4[(size_t)b*L + l] = bi;
            else
                out[ID_OFF + ((size_t)s*B + b)*L + l] = (float)bi;
            if (do_ot) {
                float m = ep->otm[0][row];
                #pragma unroll
                for (int ww = 1; ww < 8; ++ww) m = fmaxf(m, ep->otm[ww][row]);
                float Z = 0.f, Tt = 0.f;
                #pragma unroll
                for (int ww = 0; ww < 8; ++ww) {
                    float sc = expf(ep->otm[ww][row] - m);
                    Z  += ep->otz[ww][row] * sc;
                    Tt += ep->ott[ww][row] * sc;
                }
                float invx = 1.0f / (sqrtf(s2) + EPSF);
                out[OT_OFF + (size_t)b*L + l] = (Z - invx * Tt) / Z;
            }
        }
    }
    __syncthreads();

    if (tid == 0) {
        int nval = L - rowbase; if (nval > BM) nval = BM;
        float sum = 0.f;
        for (int r = 0; r < nval; ++r) sum += ep->dist[r];
        const float div = IS_TOP ? (1.0f / (float)(L * DTOP)) : (1.0f / (float)(L * DLOW));
        atomicAdd(&out[DIFF_OFF], sum * div);
    }

    if (!IS_TOP) {
        const float* embT = g_embT_lvl + (size_t)book * NE * DLOW;
        for (int it = tid; it < BM*DLOW; it += NTHREADS) {
            int r = it >> 7, c = it & 127;
            int l = rowbase + r;
            if (l >= L) continue;
            out[QUANT_OFF + (((size_t)s*B + b)*L + l)*DLOW + c] =
                embT[(size_t)ep->ind[r] * DLOW + c];
        }
    }
}

extern "C" void kernel_launch(void* const* d_in, const int* in_sizes, int n_in,
                              void* d_out, int out_size)
{
    const float* input_list = nullptr;
    const float* cb_top     = nullptr;
    const float* cb_lvl     = nullptr;
    const int*   label      = nullptr;

    for (int i = 0; i < n_in; ++i) {
        switch (in_sizes[i]) {
            case 8028160: input_list = (const float*)d_in[i]; break;
            case 491520:  cb_top     = (const float*)d_in[i]; break;
            case 3932160: cb_lvl     = (const float*)d_in[i]; break;
            case 128:     label      = (const int*)  d_in[i]; break;
        }
    }
    if (!input_list || !cb_top || !cb_lvl || !label) return;

    float* out = (float*)d_out;

    norms_kernel<<<NBOOK + 4*NBOOK, NE>>>(cb_top, cb_lvl, out);
    transpose_kernel<<<dim3(NE/32, 4, 60), dim3(32, 8)>>>(cb_lvl);
    cpre_kernel<<<dim3(16, 60), NTHREADS>>>(cb_top, cb_lvl);
    vq_gemm<true ><<<dim3(ROWBLOCKS, B),    NTHREADS>>>(input_list, cb_top, cb_lvl, label, out);
    vq_gemm<false><<<dim3(ROWBLOCKS, B, 4), NTHREADS>>>(input_list, cb_top, cb_lvl, label, out);
}

// round 13
// speedup vs baseline: 1.0762x; 1.0762x over previous
#include <cuda_runtime.h>
#include <math.h>
#include <stdint.h>

#define B      128
#define L      196
#define DTOP   64
#define DLOW   128
#define NE     512
#define NBOOK  15
#define EPSF   1e-8f
#define INV512 (1.0f/512.0f)

#define BM        32
#define KT        16
#define KDIM      64
#define NTHREADS  256
#define ROWBLOCKS 7
#define ESL_BYTES 4096u                   // per-warp slice bytes (KT*64*4)
#define E_DYN     (8u*2u*ESL_BYTES)       // 64 KB dynamic smem

#define QUANT_OFF 0ll
#define QUANT_CNT (4ll*B*L*DLOW)
#define DIFF_OFF  (QUANT_OFF + QUANT_CNT)
#define ID_OFF    (DIFF_OFF + 1)
#define ID_CNT    (4ll*B*L)
#define OT_OFF    (ID_OFF + ID_CNT)

__device__ int   g_ind4[B*L];
__device__ float g_e2_top[NBOOK*NE];
__device__ float g_e2_lvl[4*NBOOK*NE];
__device__ float g_inve0[NBOOK*NE];
__device__ float g_embT_lvl[4*NBOOK*NE*DLOW];
__device__ float g_C[60ull*NE*NE];

__device__ __forceinline__ unsigned smem_u32(const void* p) {
    unsigned r;
    asm("{.reg .u64 t; cvta.to.shared.u64 t, %1; cvt.u32.u64 %0, t;}" : "=r"(r) : "l"(p));
    return r;
}
__device__ __forceinline__ void cp16(unsigned dst, const void* src) {
    asm volatile("cp.async.cg.shared.global [%0], [%1], 16;" :: "r"(dst), "l"(src));
}
#define CP_COMMIT() asm volatile("cp.async.commit_group;" ::: "memory")
#define CP_WAIT0()  asm volatile("cp.async.wait_group 0;" ::: "memory")
#define CP_WAIT1()  asm volatile("cp.async.wait_group 1;" ::: "memory")
#define FMA2(a,x,e) asm("fma.rn.f32x2 %0, %1, %2, %0;" : "+l"(a) : "l"(x), "l"(e))

__global__ void norms_kernel(const float* __restrict__ cb_top,
                             const float* __restrict__ cb_lvl,
                             float* __restrict__ out)
{
    int k = threadIdx.x, book = blockIdx.x;
    if (book == 0 && k == 0) out[DIFF_OFF] = 0.0f;
    if (book < NBOOK) {
        const float* e = cb_top + (size_t)book * DTOP * NE;
        float s = 0.f;
        #pragma unroll 8
        for (int i = 0; i < DTOP; ++i) { float v = e[(size_t)i*NE + k]; s += v*v; }
        g_e2_top[book*NE + k] = s;
    } else {
        int bl = book - NBOOK;
        const float* e = cb_lvl + (size_t)bl * DLOW * NE;
        float s = 0.f;
        #pragma unroll 8
        for (int i = 0; i < DLOW; ++i) { float v = e[(size_t)i*NE + k]; s += v*v; }
        g_e2_lvl[bl*NE + k] = s;
        if (bl < NBOOK) g_inve0[bl*NE + k] = 1.0f / (sqrtf(s) + EPSF);
    }
}

__global__ void transpose_kernel(const float* __restrict__ cb_lvl)
{
    __shared__ float tile[32][33];
    int bl = blockIdx.z;
    int k0 = blockIdx.x * 32, d0 = blockIdx.y * 32;
    const float* src = cb_lvl + (size_t)bl * DLOW * NE;
    float* dst = g_embT_lvl + (size_t)bl * NE * DLOW;
    int tx = threadIdx.x, ty = threadIdx.y;
    #pragma unroll
    for (int dy = ty; dy < 32; dy += 8)
        tile[dy][tx] = src[(size_t)(d0 + dy) * NE + k0 + tx];
    __syncthreads();
    #pragma unroll
    for (int dy = ty; dy < 32; dy += 8)
        dst[(size_t)(k0 + dy) * DLOW + d0 + tx] = tile[tx][dy];
}

// sync-free warp-private double-buffered e slices (KT=16, 4KB/slice)
#define FILL_E_IMPL(EMB, BUF, TILE)                                            \
do {                                                                           \
    const char* esrc = (const char*)((EMB) + (size_t)(TILE) * KT * NE + w*64); \
    const unsigned dstb = e_base + (unsigned)(w*2 + (BUF)) * ESL_BYTES;        \
    _Pragma("unroll")                                                          \
    for (int q = 0; q < 8; ++q) {                                              \
        int idx = lane + q*32;                                                 \
        int kk = idx >> 4, c16 = idx & 15;                                     \
        cp16(dstb + (unsigned)(kk*256 + c16*16),                               \
             esrc + (size_t)kk*2048 + (size_t)c16*16);                         \
    }                                                                          \
    CP_COMMIT();                                                               \
} while (0)

#define COMPUTE_IMPL(BUF)                                                      \
do {                                                                           \
    const char* ek = e_cptr + (unsigned)(w*2 + (BUF))*ESL_BYTES + co*32;       \
    _Pragma("unroll")                                                          \
    for (int i = 0; i < KT; ++i) {                                             \
        ulonglong2 ea = *(const ulonglong2*)(ek + i*256);                      \
        ulonglong2 eb = *(const ulonglong2*)(ek + i*256 + 16);                 \
        float4 xa = *(const float4*)(xk + i*BM);                               \
        float4 xb = *(const float4*)(xk + i*BM + 4);                           \
        float xr8[8] = {xa.x, xa.y, xa.z, xa.w, xb.x, xb.y, xb.z, xb.w};       \
        _Pragma("unroll")                                                      \
        for (int r = 0; r < 8; ++r) {                                          \
            unsigned long long xp;                                             \
            asm("mov.b64 %0, {%1,%1};" : "=l"(xp) : "f"(xr8[r]));              \
            FMA2(acc[r][0], xp, ea.x); FMA2(acc[r][1], xp, ea.y);              \
            FMA2(acc[r][2], xp, eb.x); FMA2(acc[r][3], xp, eb.y);              \
        }                                                                      \
    }                                                                          \
    xk += KT*BM;                                                               \
} while (0)

// ---------------------------------------------------------------------------
// C table: C[book][m][n] = dot(etop[:,m], emb_lvl[book][64:128][n])
// ---------------------------------------------------------------------------
__global__ __launch_bounds__(NTHREADS, 2)
void cpre_kernel(const float* __restrict__ cb_top,
                 const float* __restrict__ cb_lvl)
{
    extern __shared__ __align__(16) char dyn_smem[];
    __shared__ __align__(16) float x_s[KDIM*BM];   // 8 KB

    const unsigned e_base = smem_u32(dyn_smem);
    const char* e_cptr = dyn_smem;

    const int mb   = blockIdx.x;
    const int book = blockIdx.y;
    const int t    = book % NBOOK;
    const int mbase = mb * BM;
    const int tid  = threadIdx.x;
    const int lane = tid & 31;
    const int w    = tid >> 5;
    const int rg8  = (lane >> 3) * 8;
    const int co   = lane & 7;
    const int colb = w * 64 + co * 8;

    const float* emb = cb_lvl + (size_t)book * DLOW * NE + (size_t)DTOP * NE;

    unsigned long long acc[8][4];
    #pragma unroll
    for (int r = 0; r < 8; ++r)
        #pragma unroll
        for (int p = 0; p < 4; ++p) acc[r][p] = 0ull;

    FILL_E_IMPL(emb, 0, 0);
    // x rows = codes m (32), cols = d (64); coalesced LDG, conflict-free STS
    for (int it = tid; it < BM*KDIM; it += NTHREADS) {
        int row = it & 31, c = it >> 5;
        x_s[c*BM + row] = cb_top[(size_t)t*DTOP*NE + (size_t)c*NE + mbase + row];
    }
    __syncthreads();

    const float* xk = x_s + rg8;
    #pragma unroll
    for (int tt = 0; tt < KDIM/KT; ++tt) {
        if (tt + 1 < KDIM/KT) { FILL_E_IMPL(emb, (tt + 1) & 1, tt + 1); CP_WAIT1(); }
        else                  { CP_WAIT0(); }
        COMPUTE_IMPL(tt & 1);
    }

    #pragma unroll
    for (int r = 0; r < 8; ++r) {
        int m = mbase + rg8 + r;
        float gv[8];
        #pragma unroll
        for (int p = 0; p < 4; ++p)
            asm("mov.b64 {%0,%1}, %2;" : "=f"(gv[2*p]), "=f"(gv[2*p+1]) : "l"(acc[r][p]));
        float* dst = g_C + ((size_t)book*NE + m)*NE + colb;
        *(float4*)dst       = make_float4(gv[0], gv[1], gv[2], gv[3]);
        *(float4*)(dst + 4) = make_float4(gv[4], gv[5], gv[6], gv[7]);
    }
}

struct Epi {
    float minv[8][BM]; int mini[8][BM];
    float otm[8][BM], otz[8][BM], ott[8][BM];
    int ind[BM]; float dist[BM];
};

// ---------------------------------------------------------------------------
// Unified VQ kernel, K=64. Top stores g_ind4 + diff; lower adds C[ind4].
// ---------------------------------------------------------------------------
template<bool IS_TOP>
__launch_bounds__(NTHREADS, 2)
__global__ void vq_gemm(const float* __restrict__ input_list,
                        const float* __restrict__ cb_top,
                        const float* __restrict__ cb_lvl,
                        const int*   __restrict__ label,
                        float*       __restrict__ out)
{
    extern __shared__ __align__(16) char dyn_smem[];   // 64 KB e slices / Epi
    __shared__ __align__(16) float x_s[KDIM*BM];       // 8 KB
    __shared__ int ind4s[BM];

    const unsigned e_base = smem_u32(dyn_smem);
    const char* e_cptr = dyn_smem;

    const int rb = blockIdx.x;
    const int b  = blockIdx.y;
    const int s  = blockIdx.z;
    const int j  = IS_TOP ? 4 : (3 - s);
    const int t  = label[b];
    const int book = j * NBOOK + t;
    const int rowbase = rb * BM;
    const int tid  = threadIdx.x;
    const int lane = tid & 31;
    const int w    = tid >> 5;
    const int rg8  = (lane >> 3) * 8;
    const int co   = lane & 7;
    const int colb = w * 64 + co * 8;

    const float* emb = IS_TOP ? (cb_top + (size_t)t * DTOP * NE)
                              : (cb_lvl + (size_t)book * DLOW * NE);

    unsigned long long acc[8][4];
    #pragma unroll
    for (int r = 0; r < 8; ++r)
        #pragma unroll
        for (int p = 0; p < 4; ++p) acc[r][p] = 0ull;

    FILL_E_IMPL(emb, 0, 0);
    {   // stage x: conflict-free STS (strided LDG is fine; L2 idle) + ind4
        const float* xin = input_list + (((size_t)j*B + b)*L)*DTOP;
        for (int it = tid; it < BM*KDIM; it += NTHREADS) {
            int row = it & 31, c = it >> 5;
            int l = rowbase + row;
            x_s[c*BM + row] = (l < L) ? xin[(size_t)l*DTOP + c] : 0.f;
        }
        if (!IS_TOP && tid < BM) {
            int l = rowbase + tid;
            ind4s[tid] = (l < L) ? g_ind4[(size_t)b*L + l] : 0;
        }
    }
    __syncthreads();

    const float* xk = x_s + rg8;
    #pragma unroll
    for (int tt = 0; tt < KDIM/KT; ++tt) {
        if (tt + 1 < KDIM/KT) { FILL_E_IMPL(emb, (tt + 1) & 1, tt + 1); CP_WAIT1(); }
        else                  { CP_WAIT0(); }
        COMPUTE_IMPL(tt & 1);
    }
    __syncthreads();   // e slices dead -> alias epilogue

    Epi* ep = (Epi*)dyn_smem;
    const float* e2p = IS_TOP ? (g_e2_top + (size_t)t * NE)
                              : (g_e2_lvl + (size_t)book * NE);
    float e2v[8];
    *(float4*)&e2v[0] = *(const float4*)&e2p[colb];
    *(float4*)&e2v[4] = *(const float4*)&e2p[colb + 4];
    const bool do_ot = (!IS_TOP) && (j == 0);
    float invev[8];
    if (do_ot) {
        const float* ip = g_inve0 + (size_t)t * NE;
        *(float4*)&invev[0] = *(const float4*)&ip[colb];
        *(float4*)&invev[4] = *(const float4*)&ip[colb + 4];
    }

    #pragma unroll
    for (int r = 0; r < 8; ++r) {
        int row = rg8 + r;
        int l = rowbase + row;

        float gv[8];
        #pragma unroll
        for (int p = 0; p < 4; ++p)
            asm("mov.b64 {%0,%1}, %2;" : "=f"(gv[2*p]), "=f"(gv[2*p+1]) : "l"(acc[r][p]));

        if (!IS_TOP) {
            const float* Cp = g_C + ((size_t)book*NE + ind4s[row])*NE + colb;
            float4 c0 = *(const float4*)Cp;
            float4 c1 = *(const float4*)(Cp + 4);
            gv[0] += c0.x; gv[1] += c0.y; gv[2] += c0.z; gv[3] += c0.w;
            gv[4] += c1.x; gv[5] += c1.y; gv[6] += c1.z; gv[7] += c1.w;
        }

        float bv = 3.4e38f; int bi = NE;
        #pragma unroll
        for (int c = 0; c < 8; ++c) {
            float v = fmaf(-2.f, gv[c], e2v[c]);
            if (v < bv || (v == bv && colb + c < bi)) { bv = v; bi = colb + c; }
        }
        #pragma unroll
        for (int o = 1; o <= 4; o <<= 1) {
            float ov = __shfl_xor_sync(0xffffffffu, bv, o);
            int   oi = __shfl_xor_sync(0xffffffffu, bi, o);
            if (ov < bv || (ov == bv && oi < bi)) { bv = ov; bi = oi; }
        }
        if (co == 0 && l < L) { ep->minv[w][row] = bv; ep->mini[w][row] = bi; }

        if (do_ot) {
            float m = -3.4e38f;
            #pragma unroll
            for (int c = 0; c < 8; ++c) m = fmaxf(m, gv[c] * INV512);
            #pragma unroll
            for (int o = 1; o <= 4; o <<= 1)
                m = fmaxf(m, __shfl_xor_sync(0xffffffffu, m, o));
            float Z = 0.f, Tt = 0.f;
            #pragma unroll
            for (int c = 0; c < 8; ++c) {
                float pe = expf(gv[c] * INV512 - m);
                Z += pe;  Tt += gv[c] * invev[c] * pe;
            }
            #pragma unroll
            for (int o = 1; o <= 4; o <<= 1) {
                Z  += __shfl_xor_sync(0xffffffffu, Z,  o);
                Tt += __shfl_xor_sync(0xffffffffu, Tt, o);
            }
            if (co == 0 && l < L) { ep->otm[w][row] = m; ep->otz[w][row] = Z; ep->ott[w][row] = Tt; }
        }
    }
    __syncthreads();

    if (tid < BM) {
        int row = tid, l = rowbase + row;
        if (l < L) {
            float s2 = 0.f;
            #pragma unroll 8
            for (int c = 0; c < KDIM; ++c) { float v = x_s[c*BM + row]; s2 += v*v; }
            if (!IS_TOP) s2 += g_e2_top[(size_t)t*NE + ind4s[row]];
            float bv = ep->minv[0][row]; int bi = ep->mini[0][row];
            #pragma unroll
            for (int ww = 1; ww < 8; ++ww) {
                float v = ep->minv[ww][row];
                if (v < bv) { bv = v; bi = ep->mini[ww][row]; }
            }
            ep->ind[row]  = bi;
            ep->dist[row] = s2 + bv;
            if (IS_TOP)
                g_ind4[(size_t)b*L + l] = bi;
            else
                out[ID_OFF + ((size_t)s*B + b)*L + l] = (float)bi;
            if (do_ot) {
                float m = ep->otm[0][row];
                #pragma unroll
                for (int ww = 1; ww < 8; ++ww) m = fmaxf(m, ep->otm[ww][row]);
                float Z = 0.f, Tt = 0.f;
                #pragma unroll
                for (int ww = 0; ww < 8; ++ww) {
                    float sc = expf(ep->otm[ww][row] - m);
                    Z  += ep->otz[ww][row] * sc;
                    Tt += ep->ott[ww][row] * sc;
                }
                float invx = 1.0f / (sqrtf(s2) + EPSF);
                out[OT_OFF + (size_t)b*L + l] = (Z - invx * Tt) / Z;
            }
        }
    }
    __syncthreads();

    if (tid == 0) {
        int nval = L - rowbase; if (nval > BM) nval = BM;
        float sum = 0.f;
        for (int r = 0; r < nval; ++r) sum += ep->dist[r];
        const float div = IS_TOP ? (1.0f / (float)(L * DTOP)) : (1.0f / (float)(L * DLOW));
        atomicAdd(&out[DIFF_OFF], sum * div);
    }

    if (!IS_TOP) {
        const float* embT = g_embT_lvl + (size_t)book * NE * DLOW;
        for (int it = tid; it < BM*DLOW; it += NTHREADS) {
            int r = it >> 7, c = it & 127;
            int l = rowbase + r;
            if (l >= L) continue;
            out[QUANT_OFF + (((size_t)s*B + b)*L + l)*DLOW + c] =
                embT[(size_t)ep->ind[r] * DLOW + c];
        }
    }
}

extern "C" void kernel_launch(void* const* d_in, const int* in_sizes, int n_in,
                              void* d_out, int out_size)
{
    const float* input_list = nullptr;
    const float* cb_top     = nullptr;
    const float* cb_lvl     = nullptr;
    const int*   label      = nullptr;

    for (int i = 0; i < n_in; ++i) {
        switch (in_sizes[i]) {
            case 8028160: input_list = (const float*)d_in[i]; break;
            case 491520:  cb_top     = (const float*)d_in[i]; break;
            case 3932160: cb_lvl     = (const float*)d_in[i]; break;
            case 128:     label      = (const int*)  d_in[i]; break;
        }
    }
    if (!input_list || !cb_top || !cb_lvl || !label) return;

    float* out = (float*)d_out;

    static int attr_set = 0;
    if (!attr_set) {
        cudaFuncSetAttribute(cpre_kernel,
                             cudaFuncAttributeMaxDynamicSharedMemorySize, E_DYN);
        cudaFuncSetAttribute(vq_gemm<true>,
                             cudaFuncAttributeMaxDynamicSharedMemorySize, E_DYN);
        cudaFuncSetAttribute(vq_gemm<false>,
                             cudaFuncAttributeMaxDynamicSharedMemorySize, E_DYN);
        attr_set = 1;
    }

    norms_kernel<<<NBOOK + 4*NBOOK, NE>>>(cb_top, cb_lvl, out);
    transpose_kernel<<<dim3(NE/32, 4, 60), dim3(32, 8)>>>(cb_lvl);
    cpre_kernel<<<dim3(16, 60), NTHREADS, E_DYN>>>(cb_top, cb_lvl);
    vq_gemm<true ><<<dim3(ROWBLOCKS, B),    NTHREADS, E_DYN>>>(input_list, cb_top, cb_lvl, label, out);
    vq_gemm<false><<<dim3(ROWBLOCKS, B, 4), NTHREADS, E_DYN>>>(input_list, cb_top, cb_lvl, label, out);
}

// round 14
// speedup vs baseline: 1.1148x; 1.0358x over previous
#include <cuda_runtime.h>
#include <math.h>
#include <stdint.h>

#define B      128
#define L      196
#define DTOP   64
#define DLOW   128
#define NE     512
#define NBOOK  15
#define EPSF   1e-8f
#define INV512 (1.0f/512.0f)

#define BM        32
#define KT        16
#define KDIM      64
#define NTHREADS  256
#define ROWBLOCKS 7
#define ESL_BYTES 4096u                   // per-warp slice bytes (KT*64*4)
#define E_DYN     (8u*2u*ESL_BYTES)       // 64 KB dynamic smem

#define QUANT_OFF 0ll
#define QUANT_CNT (4ll*B*L*DLOW)
#define DIFF_OFF  (QUANT_OFF + QUANT_CNT)
#define ID_OFF    (DIFF_OFF + 1)
#define ID_CNT    (4ll*B*L)
#define OT_OFF    (ID_OFF + ID_CNT)

__device__ int   g_ind4[B*L];
__device__ float g_e2_top[NBOOK*NE];
__device__ float g_e2_lvl[4*NBOOK*NE];
__device__ float g_inve0[NBOOK*NE];
__device__ float g_embT_lvl[4*NBOOK*NE*DLOW];
__device__ float g_C[60ull*NE*NE];

__device__ __forceinline__ unsigned smem_u32(const void* p) {
    unsigned r;
    asm("{.reg .u64 t; cvta.to.shared.u64 t, %1; cvt.u32.u64 %0, t;}" : "=r"(r) : "l"(p));
    return r;
}
__device__ __forceinline__ void cp16(unsigned dst, const void* src) {
    asm volatile("cp.async.cg.shared.global [%0], [%1], 16;" :: "r"(dst), "l"(src));
}
#define CP_COMMIT() asm volatile("cp.async.commit_group;" ::: "memory")
#define CP_WAIT0()  asm volatile("cp.async.wait_group 0;" ::: "memory")
#define CP_WAIT1()  asm volatile("cp.async.wait_group 1;" ::: "memory")
#define FMA2(a,x,e) asm("fma.rn.f32x2 %0, %1, %2, %0;" : "+l"(a) : "l"(x), "l"(e))

__global__ void norms_kernel(const float* __restrict__ cb_top,
                             const float* __restrict__ cb_lvl,
                             float* __restrict__ out)
{
    int k = threadIdx.x, book = blockIdx.x;
    if (book == 0 && k == 0) out[DIFF_OFF] = 0.0f;
    if (book < NBOOK) {
        const float* e = cb_top + (size_t)book * DTOP * NE;
        float s = 0.f;
        #pragma unroll 8
        for (int i = 0; i < DTOP; ++i) { float v = e[(size_t)i*NE + k]; s += v*v; }
        g_e2_top[book*NE + k] = s;
    } else {
        int bl = book - NBOOK;
        const float* e = cb_lvl + (size_t)bl * DLOW * NE;
        float s = 0.f;
        #pragma unroll 8
        for (int i = 0; i < DLOW; ++i) { float v = e[(size_t)i*NE + k]; s += v*v; }
        g_e2_lvl[bl*NE + k] = s;
        if (bl < NBOOK) g_inve0[bl*NE + k] = 1.0f / (sqrtf(s) + EPSF);
    }
}

__global__ void transpose_kernel(const float* __restrict__ cb_lvl)
{
    __shared__ float tile[32][33];
    int bl = blockIdx.z;
    int k0 = blockIdx.x * 32, d0 = blockIdx.y * 32;
    const float* src = cb_lvl + (size_t)bl * DLOW * NE;
    float* dst = g_embT_lvl + (size_t)bl * NE * DLOW;
    int tx = threadIdx.x, ty = threadIdx.y;
    #pragma unroll
    for (int dy = ty; dy < 32; dy += 8)
        tile[dy][tx] = src[(size_t)(d0 + dy) * NE + k0 + tx];
    __syncthreads();
    #pragma unroll
    for (int dy = ty; dy < 32; dy += 8)
        dst[(size_t)(k0 + dy) * DLOW + d0 + tx] = tile[tx][dy];
}

// sync-free warp-private double-buffered e slices (KT=16, 4KB/slice)
#define FILL_E_IMPL(EMB, BUF, TILE)                                            \
do {                                                                           \
    const char* esrc = (const char*)((EMB) + (size_t)(TILE) * KT * NE + w*64); \
    const unsigned dstb = e_base + (unsigned)(w*2 + (BUF)) * ESL_BYTES;        \
    _Pragma("unroll")                                                          \
    for (int q = 0; q < 8; ++q) {                                              \
        int idx = lane + q*32;                                                 \
        int kk = idx >> 4, c16 = idx & 15;                                     \
        cp16(dstb + (unsigned)(kk*256 + c16*16),                               \
             esrc + (size_t)kk*2048 + (size_t)c16*16);                         \
    }                                                                          \
    CP_COMMIT();                                                               \
} while (0)

#define COMPUTE_IMPL(BUF)                                                      \
do {                                                                           \
    const char* ek = e_cptr + (unsigned)(w*2 + (BUF))*ESL_BYTES + co*32;       \
    _Pragma("unroll")                                                          \
    for (int i = 0; i < KT; ++i) {                                             \
        ulonglong2 ea = *(const ulonglong2*)(ek + i*256);                      \
        ulonglong2 eb = *(const ulonglong2*)(ek + i*256 + 16);                 \
        float4 xa = *(const float4*)(xk + i*BM);                               \
        float4 xb = *(const float4*)(xk + i*BM + 4);                           \
        float xr8[8] = {xa.x, xa.y, xa.z, xa.w, xb.x, xb.y, xb.z, xb.w};       \
        _Pragma("unroll")                                                      \
        for (int r = 0; r < 8; ++r) {                                          \
            unsigned long long xp;                                             \
            asm("mov.b64 %0, {%1,%1};" : "=l"(xp) : "f"(xr8[r]));              \
            FMA2(acc[r][0], xp, ea.x); FMA2(acc[r][1], xp, ea.y);              \
            FMA2(acc[r][2], xp, eb.x); FMA2(acc[r][3], xp, eb.y);              \
        }                                                                      \
    }                                                                          \
    xk += KT*BM;                                                               \
} while (0)

// ---------------------------------------------------------------------------
// C table: C[book][m][n] = dot(etop[:,m], emb_lvl[book][64:128][n])
// ---------------------------------------------------------------------------
__global__ __launch_bounds__(NTHREADS, 2)
void cpre_kernel(const float* __restrict__ cb_top,
                 const float* __restrict__ cb_lvl)
{
    extern __shared__ __align__(16) char dyn_smem[];
    __shared__ __align__(16) float x_s[KDIM*BM];   // 8 KB

    const unsigned e_base = smem_u32(dyn_smem);
    const char* e_cptr = dyn_smem;

    const int mb   = blockIdx.x;
    const int book = blockIdx.y;
    const int t    = book % NBOOK;
    const int mbase = mb * BM;
    const int tid  = threadIdx.x;
    const int lane = tid & 31;
    const int w    = tid >> 5;
    const int rg8  = (lane >> 3) * 8;
    const int co   = lane & 7;
    const int colb = w * 64 + co * 8;

    const float* emb = cb_lvl + (size_t)book * DLOW * NE + (size_t)DTOP * NE;

    unsigned long long acc[8][4];
    #pragma unroll
    for (int r = 0; r < 8; ++r)
        #pragma unroll
        for (int p = 0; p < 4; ++p) acc[r][p] = 0ull;

    FILL_E_IMPL(emb, 0, 0);
    for (int it = tid; it < BM*KDIM; it += NTHREADS) {
        int row = it & 31, c = it >> 5;
        x_s[c*BM + row] = cb_top[(size_t)t*DTOP*NE + (size_t)c*NE + mbase + row];
    }
    __syncthreads();

    const float* xk = x_s + rg8;
    #pragma unroll
    for (int tt = 0; tt < KDIM/KT; ++tt) {
        if (tt + 1 < KDIM/KT) { FILL_E_IMPL(emb, (tt + 1) & 1, tt + 1); CP_WAIT1(); }
        else                  { CP_WAIT0(); }
        COMPUTE_IMPL(tt & 1);
    }

    #pragma unroll
    for (int r = 0; r < 8; ++r) {
        int m = mbase + rg8 + r;
        float gv[8];
        #pragma unroll
        for (int p = 0; p < 4; ++p)
            asm("mov.b64 {%0,%1}, %2;" : "=f"(gv[2*p]), "=f"(gv[2*p+1]) : "l"(acc[r][p]));
        float* dst = g_C + ((size_t)book*NE + m)*NE + colb;
        *(float4*)dst       = make_float4(gv[0], gv[1], gv[2], gv[3]);
        *(float4*)(dst + 4) = make_float4(gv[4], gv[5], gv[6], gv[7]);
    }
}

struct Epi {
    float minv[8][BM]; int mini[8][BM];
    float otm[8][BM], otz[8][BM], ott[8][BM];
    int ind[BM]; float dist[BM];
};

// ---------------------------------------------------------------------------
// Unified VQ kernel, K=64. Top stores g_ind4 + diff; lower adds C[ind4].
// ---------------------------------------------------------------------------
template<bool IS_TOP>
__launch_bounds__(NTHREADS, 2)
__global__ void vq_gemm(const float* __restrict__ input_list,
                        const float* __restrict__ cb_top,
                        const float* __restrict__ cb_lvl,
                        const int*   __restrict__ label,
                        float*       __restrict__ out)
{
    extern __shared__ __align__(16) char dyn_smem[];   // 64 KB e slices / Epi
    __shared__ __align__(16) float x_s[KDIM*BM];       // 8 KB
    __shared__ int ind4s[BM];

    const unsigned e_base = smem_u32(dyn_smem);
    const char* e_cptr = dyn_smem;

    const int rb = blockIdx.x;
    const int b  = blockIdx.y;
    const int s  = blockIdx.z;
    const int j  = IS_TOP ? 4 : (3 - s);
    const int t  = label[b];
    const int book = j * NBOOK + t;
    const int rowbase = rb * BM;
    const int tid  = threadIdx.x;
    const int lane = tid & 31;
    const int w    = tid >> 5;
    const int rg8  = (lane >> 3) * 8;
    const int co   = lane & 7;
    const int colb = w * 64 + co * 8;

    const float* emb = IS_TOP ? (cb_top + (size_t)t * DTOP * NE)
                              : (cb_lvl + (size_t)book * DLOW * NE);

    unsigned long long acc[8][4];
    #pragma unroll
    for (int r = 0; r < 8; ++r)
        #pragma unroll
        for (int p = 0; p < 4; ++p) acc[r][p] = 0ull;

    FILL_E_IMPL(emb, 0, 0);
    {
        const float* xin = input_list + (((size_t)j*B + b)*L)*DTOP;
        for (int it = tid; it < BM*KDIM; it += NTHREADS) {
            int row = it & 31, c = it >> 5;
            int l = rowbase + row;
            x_s[c*BM + row] = (l < L) ? xin[(size_t)l*DTOP + c] : 0.f;
        }
        if (!IS_TOP && tid < BM) {
            int l = rowbase + tid;
            ind4s[tid] = (l < L) ? g_ind4[(size_t)b*L + l] : 0;
        }
    }
    __syncthreads();

    const float* xk = x_s + rg8;
    #pragma unroll
    for (int tt = 0; tt < KDIM/KT; ++tt) {
        if (tt + 1 < KDIM/KT) { FILL_E_IMPL(emb, (tt + 1) & 1, tt + 1); CP_WAIT1(); }
        else                  { CP_WAIT0(); }
        COMPUTE_IMPL(tt & 1);
    }
    __syncthreads();   // e slices dead -> alias epilogue

    Epi* ep = (Epi*)dyn_smem;
    const float* e2p = IS_TOP ? (g_e2_top + (size_t)t * NE)
                              : (g_e2_lvl + (size_t)book * NE);
    float e2v[8];
    *(float4*)&e2v[0] = *(const float4*)&e2p[colb];
    *(float4*)&e2v[4] = *(const float4*)&e2p[colb + 4];
    const bool do_ot = (!IS_TOP) && (j == 0);
    float invev[8];
    if (do_ot) {
        const float* ip = g_inve0 + (size_t)t * NE;
        *(float4*)&invev[0] = *(const float4*)&ip[colb];
        *(float4*)&invev[4] = *(const float4*)&ip[colb + 4];
    }

    #pragma unroll
    for (int r = 0; r < 8; ++r) {
        int row = rg8 + r;
        int l = rowbase + row;

        float gv[8];
        #pragma unroll
        for (int p = 0; p < 4; ++p)
            asm("mov.b64 {%0,%1}, %2;" : "=f"(gv[2*p]), "=f"(gv[2*p+1]) : "l"(acc[r][p]));

        if (!IS_TOP) {
            const float* Cp = g_C + ((size_t)book*NE + ind4s[row])*NE + colb;
            float4 c0 = *(const float4*)Cp;
            float4 c1 = *(const float4*)(Cp + 4);
            gv[0] += c0.x; gv[1] += c0.y; gv[2] += c0.z; gv[3] += c0.w;
            gv[4] += c1.x; gv[5] += c1.y; gv[6] += c1.z; gv[7] += c1.w;
        }

        float bv = 3.4e38f; int bi = NE;
        #pragma unroll
        for (int c = 0; c < 8; ++c) {
            float v = fmaf(-2.f, gv[c], e2v[c]);
            if (v < bv || (v == bv && colb + c < bi)) { bv = v; bi = colb + c; }
        }
        #pragma unroll
        for (int o = 1; o <= 4; o <<= 1) {
            float ov = __shfl_xor_sync(0xffffffffu, bv, o);
            int   oi = __shfl_xor_sync(0xffffffffu, bi, o);
            if (ov < bv || (ov == bv && oi < bi)) { bv = ov; bi = oi; }
        }
        if (co == 0 && l < L) { ep->minv[w][row] = bv; ep->mini[w][row] = bi; }

        if (do_ot) {
            float m = -3.4e38f;
            #pragma unroll
            for (int c = 0; c < 8; ++c) m = fmaxf(m, gv[c] * INV512);
            #pragma unroll
            for (int o = 1; o <= 4; o <<= 1)
                m = fmaxf(m, __shfl_xor_sync(0xffffffffu, m, o));
            float Z = 0.f, Tt = 0.f;
            #pragma unroll
            for (int c = 0; c < 8; ++c) {
                float pe = expf(gv[c] * INV512 - m);
                Z += pe;  Tt += gv[c] * invev[c] * pe;
            }
            #pragma unroll
            for (int o = 1; o <= 4; o <<= 1) {
                Z  += __shfl_xor_sync(0xffffffffu, Z,  o);
                Tt += __shfl_xor_sync(0xffffffffu, Tt, o);
            }
            if (co == 0 && l < L) { ep->otm[w][row] = m; ep->otz[w][row] = Z; ep->ott[w][row] = Tt; }
        }
    }
    __syncthreads();

    if (tid < BM) {
        int row = tid, l = rowbase + row;
        if (l < L) {
            float s2 = 0.f;
            #pragma unroll 8
            for (int c = 0; c < KDIM; ++c) { float v = x_s[c*BM + row]; s2 += v*v; }
            if (!IS_TOP) s2 += g_e2_top[(size_t)t*NE + ind4s[row]];
            float bv = ep->minv[0][row]; int bi = ep->mini[0][row];
            #pragma unroll
            for (int ww = 1; ww < 8; ++ww) {
                float v = ep->minv[ww][row];
                if (v < bv) { bv = v; bi = ep->mini[ww][row]; }
            }
            ep->ind[row]  = bi;
            ep->dist[row] = s2 + bv;
            if (IS_TOP)
                g_ind4[(size_t)b*L + l] = bi;
            else
                out[ID_OFF + ((size_t)s*B + b)*L + l] = (float)bi;
            if (do_ot) {
                float m = ep->otm[0][row];
                #pragma unroll
                for (int ww = 1; ww < 8; ++ww) m = fmaxf(m, ep->otm[ww][row]);
                float Z = 0.f, Tt = 0.f;
                #pragma unroll
                for (int ww = 0; ww < 8; ++ww) {
                    float sc = expf(ep->otm[ww][row] - m);
                    Z  += ep->otz[ww][row] * sc;
                    Tt += ep->ott[ww][row] * sc;
                }
                float invx = 1.0f / (sqrtf(s2) + EPSF);
                out[OT_OFF + (size_t)b*L + l] = (Z - invx * Tt) / Z;
            }
        }
    }
    __syncthreads();

    if (tid == 0) {
        int nval = L - rowbase; if (nval > BM) nval = BM;
        float sum = 0.f;
        for (int r = 0; r < nval; ++r) sum += ep->dist[r];
        const float div = IS_TOP ? (1.0f / (float)(L * DTOP)) : (1.0f / (float)(L * DLOW));
        atomicAdd(&out[DIFF_OFF], sum * div);
    }

    if (!IS_TOP) {
        const float* embT = g_embT_lvl + (size_t)book * NE * DLOW;
        for (int it = tid; it < BM*DLOW; it += NTHREADS) {
            int r = it >> 7, c = it & 127;
            int l = rowbase + r;
            if (l >= L) continue;
            out[QUANT_OFF + (((size_t)s*B + b)*L + l)*DLOW + c] =
                embT[(size_t)ep->ind[r] * DLOW + c];
        }
    }
}

extern "C" void kernel_launch(void* const* d_in, const int* in_sizes, int n_in,
                              void* d_out, int out_size)
{
    const float* input_list = nullptr;
    const float* cb_top     = nullptr;
    const float* cb_lvl     = nullptr;
    const int*   label      = nullptr;

    for (int i = 0; i < n_in; ++i) {
        switch (in_sizes[i]) {
            case 8028160: input_list = (const float*)d_in[i]; break;
            case 491520:  cb_top     = (const float*)d_in[i]; break;
            case 3932160: cb_lvl     = (const float*)d_in[i]; break;
            case 128:     label      = (const int*)  d_in[i]; break;
        }
    }
    if (!input_list || !cb_top || !cb_lvl || !label) return;

    float* out = (float*)d_out;

    // one-time setup (first call is the uncaptured correctness run)
    static cudaStream_t s1 = nullptr, s2 = nullptr;
    static cudaEvent_t evRoot = nullptr, ev1 = nullptr, ev2 = nullptr;
    static int attr_set = 0;
    if (!attr_set) {
        cudaFuncSetAttribute(cpre_kernel,
                             cudaFuncAttributeMaxDynamicSharedMemorySize, E_DYN);
        cudaFuncSetAttribute(vq_gemm<true>,
                             cudaFuncAttributeMaxDynamicSharedMemorySize, E_DYN);
        cudaFuncSetAttribute(vq_gemm<false>,
                             cudaFuncAttributeMaxDynamicSharedMemorySize, E_DYN);
        cudaStreamCreateWithFlags(&s1, cudaStreamNonBlocking);
        cudaStreamCreateWithFlags(&s2, cudaStreamNonBlocking);
        cudaEventCreateWithFlags(&evRoot, cudaEventDisableTiming);
        cudaEventCreateWithFlags(&ev1, cudaEventDisableTiming);
        cudaEventCreateWithFlags(&ev2, cudaEventDisableTiming);
        attr_set = 1;
    }

    // fork side streams from the (captured) default stream
    cudaEventRecord(evRoot, 0);
    cudaStreamWaitEvent(s1, evRoot, 0);
    cudaStreamWaitEvent(s2, evRoot, 0);

    // s1: codebook transpose (independent)
    transpose_kernel<<<dim3(NE/32, 4, 60), dim3(32, 8), 0, s1>>>(cb_lvl);
    cudaEventRecord(ev1, s1);

    // s2: C-table precompute (independent)
    cpre_kernel<<<dim3(16, 60), NTHREADS, E_DYN, s2>>>(cb_top, cb_lvl);
    cudaEventRecord(ev2, s2);

    // default stream: norms -> top-level VQ (needs g_e2_top)
    norms_kernel<<<NBOOK + 4*NBOOK, NE>>>(cb_top, cb_lvl, out);
    vq_gemm<true><<<dim3(ROWBLOCKS, B), NTHREADS, E_DYN>>>(input_list, cb_top, cb_lvl, label, out);

    // join: lower levels need transpose (gather), C table, norms, ind4
    cudaStreamWaitEvent(0, ev1, 0);
    cudaStreamWaitEvent(0, ev2, 0);
    vq_gemm<false><<<dim3(ROWBLOCKS, B, 4), NTHREADS, E_DYN>>>(input_list, cb_top, cb_lvl, label, out);
}

// round 15
// speedup vs baseline: 1.1702x; 1.0497x over previous
#include <cuda_runtime.h>
#include <math.h>
#include <stdint.h>

#define B      128
#define L      196
#define DTOP   64
#define DLOW   128
#define NE     512
#define NBOOK  15
#define EPSF   1e-8f
#define INV512 (1.0f/512.0f)

#define BM        40          // vq row-block (lane = 10 rows x 8 cols)
#define CBM       32          // cpre row-block (lane = 8 rows x 8 cols)
#define KT        16
#define KDIM      64
#define NTHREADS  256
#define ROWBLOCKS 5           // ceil(196/40)
#define ESL_BYTES 4096u
#define E_DYN     (8u*2u*ESL_BYTES)   // 64 KB dynamic smem

#define QUANT_OFF 0ll
#define QUANT_CNT (4ll*B*L*DLOW)
#define DIFF_OFF  (QUANT_OFF + QUANT_CNT)
#define ID_OFF    (DIFF_OFF + 1)
#define ID_CNT    (4ll*B*L)
#define OT_OFF    (ID_OFF + ID_CNT)

__device__ int   g_ind4[B*L];
__device__ float g_e2_top[NBOOK*NE];
__device__ float g_e2_lvl[4*NBOOK*NE];
__device__ float g_inve0[NBOOK*NE];
__device__ float g_embT_lvl[4*NBOOK*NE*DLOW];
__device__ float g_C[60ull*NE*NE];

__device__ __forceinline__ unsigned smem_u32(const void* p) {
    unsigned r;
    asm("{.reg .u64 t; cvta.to.shared.u64 t, %1; cvt.u32.u64 %0, t;}" : "=r"(r) : "l"(p));
    return r;
}
__device__ __forceinline__ void cp16(unsigned dst, const void* src) {
    asm volatile("cp.async.cg.shared.global [%0], [%1], 16;" :: "r"(dst), "l"(src));
}
#define CP_COMMIT() asm volatile("cp.async.commit_group;" ::: "memory")
#define CP_WAIT0()  asm volatile("cp.async.wait_group 0;" ::: "memory")
#define CP_WAIT1()  asm volatile("cp.async.wait_group 1;" ::: "memory")
#define FMA2(a,x,e) asm("fma.rn.f32x2 %0, %1, %2, %0;" : "+l"(a) : "l"(x), "l"(e))

__global__ void norms_kernel(const float* __restrict__ cb_top,
                             const float* __restrict__ cb_lvl,
                             float* __restrict__ out)
{
    int k = threadIdx.x, book = blockIdx.x;
    if (book == 0 && k == 0) out[DIFF_OFF] = 0.0f;
    if (book < NBOOK) {
        const float* e = cb_top + (size_t)book * DTOP * NE;
        float s = 0.f;
        #pragma unroll 8
        for (int i = 0; i < DTOP; ++i) { float v = e[(size_t)i*NE + k]; s += v*v; }
        g_e2_top[book*NE + k] = s;
    } else {
        int bl = book - NBOOK;
        const float* e = cb_lvl + (size_t)bl * DLOW * NE;
        float s = 0.f;
        #pragma unroll 8
        for (int i = 0; i < DLOW; ++i) { float v = e[(size_t)i*NE + k]; s += v*v; }
        g_e2_lvl[bl*NE + k] = s;
        if (bl < NBOOK) g_inve0[bl*NE + k] = 1.0f / (sqrtf(s) + EPSF);
    }
}

__global__ void transpose_kernel(const float* __restrict__ cb_lvl)
{
    __shared__ float tile[32][33];
    int bl = blockIdx.z;
    int k0 = blockIdx.x * 32, d0 = blockIdx.y * 32;
    const float* src = cb_lvl + (size_t)bl * DLOW * NE;
    float* dst = g_embT_lvl + (size_t)bl * NE * DLOW;
    int tx = threadIdx.x, ty = threadIdx.y;
    #pragma unroll
    for (int dy = ty; dy < 32; dy += 8)
        tile[dy][tx] = src[(size_t)(d0 + dy) * NE + k0 + tx];
    __syncthreads();
    #pragma unroll
    for (int dy = ty; dy < 32; dy += 8)
        dst[(size_t)(k0 + dy) * DLOW + d0 + tx] = tile[tx][dy];
}

// e-slice fill: identical for all GEMM kernels (warp-private, double-buffered)
#define FILL_E_IMPL(EMB, BUF, TILE)                                            \
do {                                                                           \
    const char* esrc = (const char*)((EMB) + (size_t)(TILE) * KT * NE + w*64); \
    const unsigned dstb = e_base + (unsigned)(w*2 + (BUF)) * ESL_BYTES;        \
    _Pragma("unroll")                                                          \
    for (int q = 0; q < 8; ++q) {                                              \
        int idx = lane + q*32;                                                 \
        int kk = idx >> 4, c16 = idx & 15;                                     \
        cp16(dstb + (unsigned)(kk*256 + c16*16),                               \
             esrc + (size_t)kk*2048 + (size_t)c16*16);                         \
    }                                                                          \
    CP_COMMIT();                                                               \
} while (0)

// ---------------------------------------------------------------------------
// C table: proven 8x8 lane-tile geometry (BM=32)
// ---------------------------------------------------------------------------
#define CPRE_COMPUTE(BUF)                                                      \
do {                                                                           \
    const char* ek = e_cptr + (unsigned)(w*2 + (BUF))*ESL_BYTES + co*32;       \
    _Pragma("unroll")                                                          \
    for (int i = 0; i < KT; ++i) {                                             \
        ulonglong2 ea = *(const ulonglong2*)(ek + i*256);                      \
        ulonglong2 eb = *(const ulonglong2*)(ek + i*256 + 16);                 \
        float4 xa = *(const float4*)(xk + i*CBM);                              \
        float4 xb = *(const float4*)(xk + i*CBM + 4);                          \
        float xr8[8] = {xa.x, xa.y, xa.z, xa.w, xb.x, xb.y, xb.z, xb.w};       \
        _Pragma("unroll")                                                      \
        for (int r = 0; r < 8; ++r) {                                          \
            unsigned long long xp;                                             \
            asm("mov.b64 %0, {%1,%1};" : "=l"(xp) : "f"(xr8[r]));              \
            FMA2(acc[r][0], xp, ea.x); FMA2(acc[r][1], xp, ea.y);              \
            FMA2(acc[r][2], xp, eb.x); FMA2(acc[r][3], xp, eb.y);              \
        }                                                                      \
    }                                                                          \
    xk += KT*CBM;                                                              \
} while (0)

__global__ __launch_bounds__(NTHREADS, 2)
void cpre_kernel(const float* __restrict__ cb_top,
                 const float* __restrict__ cb_lvl)
{
    extern __shared__ __align__(16) char dyn_smem[];
    __shared__ __align__(16) float x_s[KDIM*CBM];

    const unsigned e_base = smem_u32(dyn_smem);
    const char* e_cptr = dyn_smem;

    const int mb   = blockIdx.x;
    const int book = blockIdx.y;
    const int t    = book % NBOOK;
    const int mbase = mb * CBM;
    const int tid  = threadIdx.x;
    const int lane = tid & 31;
    const int w    = tid >> 5;
    const int rg8  = (lane >> 3) * 8;
    const int co   = lane & 7;
    const int colb = w * 64 + co * 8;

    const float* emb = cb_lvl + (size_t)book * DLOW * NE + (size_t)DTOP * NE;

    unsigned long long acc[8][4];
    #pragma unroll
    for (int r = 0; r < 8; ++r)
        #pragma unroll
        for (int p = 0; p < 4; ++p) acc[r][p] = 0ull;

    FILL_E_IMPL(emb, 0, 0);
    for (int it = tid; it < CBM*KDIM; it += NTHREADS) {
        int row = it & 31, c = it >> 5;
        x_s[c*CBM + row] = cb_top[(size_t)t*DTOP*NE + (size_t)c*NE + mbase + row];
    }
    __syncthreads();

    const float* xk = x_s + rg8;
    #pragma unroll
    for (int tt = 0; tt < KDIM/KT; ++tt) {
        if (tt + 1 < KDIM/KT) { FILL_E_IMPL(emb, (tt + 1) & 1, tt + 1); CP_WAIT1(); }
        else                  { CP_WAIT0(); }
        CPRE_COMPUTE(tt & 1);
    }

    #pragma unroll
    for (int r = 0; r < 8; ++r) {
        int m = mbase + rg8 + r;
        float gv[8];
        #pragma unroll
        for (int p = 0; p < 4; ++p)
            asm("mov.b64 {%0,%1}, %2;" : "=f"(gv[2*p]), "=f"(gv[2*p+1]) : "l"(acc[r][p]));
        float* dst = g_C + ((size_t)book*NE + m)*NE + colb;
        *(float4*)dst       = make_float4(gv[0], gv[1], gv[2], gv[3]);
        *(float4*)(dst + 4) = make_float4(gv[4], gv[5], gv[6], gv[7]);
    }
}

struct Epi {
    float minv[8][BM]; int mini[8][BM];
    float otm[8][BM], otz[8][BM], ott[8][BM];
    int ind[BM]; float dist[BM];
};

// ---------------------------------------------------------------------------
// Unified VQ kernel, K=64. Lane = 10 rows (rg + 4i) x 8 cols. BM=40.
// ---------------------------------------------------------------------------
#define VQ_COMPUTE(BUF)                                                        \
do {                                                                           \
    const char* ek = e_cptr + (unsigned)(w*2 + (BUF))*ESL_BYTES + co*32;       \
    _Pragma("unroll")                                                          \
    for (int i = 0; i < KT; ++i) {                                             \
        ulonglong2 ea = *(const ulonglong2*)(ek + i*256);                      \
        ulonglong2 eb = *(const ulonglong2*)(ek + i*256 + 16);                 \
        _Pragma("unroll")                                                      \
        for (int r = 0; r < 10; ++r) {                                         \
            float xv = xk[i*BM + r*4];                                         \
            unsigned long long xp;                                             \
            asm("mov.b64 %0, {%1,%1};" : "=l"(xp) : "f"(xv));                  \
            FMA2(acc[r][0], xp, ea.x); FMA2(acc[r][1], xp, ea.y);              \
            FMA2(acc[r][2], xp, eb.x); FMA2(acc[r][3], xp, eb.y);              \
        }                                                                      \
    }                                                                          \
    xk += KT*BM;                                                               \
} while (0)

template<bool IS_TOP>
__launch_bounds__(NTHREADS, 2)
__global__ void vq_gemm(const float* __restrict__ input_list,
                        const float* __restrict__ cb_top,
                        const float* __restrict__ cb_lvl,
                        const int*   __restrict__ label,
                        float*       __restrict__ out)
{
    extern __shared__ __align__(16) char dyn_smem[];   // 64 KB e slices / Epi
    __shared__ __align__(16) float x_s[KDIM*BM];       // 10 KB
    __shared__ int ind4s[BM];

    const unsigned e_base = smem_u32(dyn_smem);
    const char* e_cptr = dyn_smem;

    const int rb = blockIdx.x;
    const int b  = blockIdx.y;
    const int s  = blockIdx.z;
    const int j  = IS_TOP ? 4 : (3 - s);
    const int t  = label[b];
    const int book = j * NBOOK + t;
    const int rowbase = rb * BM;
    const int tid  = threadIdx.x;
    const int lane = tid & 31;
    const int w    = tid >> 5;
    const int rg   = lane >> 3;        // rows rg, rg+4, ..., rg+36
    const int co   = lane & 7;
    const int colb = w * 64 + co * 8;

    const float* emb = IS_TOP ? (cb_top + (size_t)t * DTOP * NE)
                              : (cb_lvl + (size_t)book * DLOW * NE);

    unsigned long long acc[10][4];   // 10 rows x 4 col-pairs = 80 regs
    #pragma unroll
    for (int r = 0; r < 10; ++r)
        #pragma unroll
        for (int p = 0; p < 4; ++p) acc[r][p] = 0ull;

    FILL_E_IMPL(emb, 0, 0);
    {   // stage x (rows beyond L zero-padded) + ind4
        const float* xin = input_list + (((size_t)j*B + b)*L)*DTOP;
        for (int it = tid; it < BM*KDIM; it += NTHREADS) {
            int row = it % BM, c = it / BM;
            int l = rowbase + row;
            x_s[c*BM + row] = (l < L) ? xin[(size_t)l*DTOP + c] : 0.f;
        }
        if (!IS_TOP && tid < BM) {
            int l = rowbase + tid;
            ind4s[tid] = (l < L) ? g_ind4[(size_t)b*L + l] : 0;
        }
    }
    __syncthreads();

    const float* xk = x_s + rg;
    #pragma unroll
    for (int tt = 0; tt < KDIM/KT; ++tt) {
        if (tt + 1 < KDIM/KT) { FILL_E_IMPL(emb, (tt + 1) & 1, tt + 1); CP_WAIT1(); }
        else                  { CP_WAIT0(); }
        VQ_COMPUTE(tt & 1);
    }
    __syncthreads();   // e slices dead -> alias epilogue

    Epi* ep = (Epi*)dyn_smem;
    const float* e2p = IS_TOP ? (g_e2_top + (size_t)t * NE)
                              : (g_e2_lvl + (size_t)book * NE);
    float e2v[8];
    *(float4*)&e2v[0] = *(const float4*)&e2p[colb];
    *(float4*)&e2v[4] = *(const float4*)&e2p[colb + 4];
    const bool do_ot = (!IS_TOP) && (j == 0);
    float invev[8];
    if (do_ot) {
        const float* ip = g_inve0 + (size_t)t * NE;
        *(float4*)&invev[0] = *(const float4*)&ip[colb];
        *(float4*)&invev[4] = *(const float4*)&ip[colb + 4];
    }

    #pragma unroll
    for (int r = 0; r < 10; ++r) {
        int row = rg + r*4;
        int l = rowbase + row;

        float gv[8];
        #pragma unroll
        for (int p = 0; p < 4; ++p)
            asm("mov.b64 {%0,%1}, %2;" : "=f"(gv[2*p]), "=f"(gv[2*p+1]) : "l"(acc[r][p]));

        if (!IS_TOP) {
            const float* Cp = g_C + ((size_t)book*NE + ind4s[row])*NE + colb;
            float4 c0 = *(const float4*)Cp;
            float4 c1 = *(const float4*)(Cp + 4);
            gv[0] += c0.x; gv[1] += c0.y; gv[2] += c0.z; gv[3] += c0.w;
            gv[4] += c1.x; gv[5] += c1.y; gv[6] += c1.z; gv[7] += c1.w;
        }

        float bv = 3.4e38f; int bi = NE;
        #pragma unroll
        for (int c = 0; c < 8; ++c) {
            float v = fmaf(-2.f, gv[c], e2v[c]);
            if (v < bv || (v == bv && colb + c < bi)) { bv = v; bi = colb + c; }
        }
        // reduce across the 8 co lanes (xor bits 0..2 stay within rg group)
        #pragma unroll
        for (int o = 1; o <= 4; o <<= 1) {
            float ov = __shfl_xor_sync(0xffffffffu, bv, o);
            int   oi = __shfl_xor_sync(0xffffffffu, bi, o);
            if (ov < bv || (ov == bv && oi < bi)) { bv = ov; bi = oi; }
        }
        if (co == 0 && l < L) { ep->minv[w][row] = bv; ep->mini[w][row] = bi; }

        if (do_ot) {
            float m = -3.4e38f;
            #pragma unroll
            for (int c = 0; c < 8; ++c) m = fmaxf(m, gv[c] * INV512);
            #pragma unroll
            for (int o = 1; o <= 4; o <<= 1)
                m = fmaxf(m, __shfl_xor_sync(0xffffffffu, m, o));
            float Z = 0.f, Tt = 0.f;
            #pragma unroll
            for (int c = 0; c < 8; ++c) {
                float pe = expf(gv[c] * INV512 - m);
                Z += pe;  Tt += gv[c] * invev[c] * pe;
            }
            #pragma unroll
            for (int o = 1; o <= 4; o <<= 1) {
                Z  += __shfl_xor_sync(0xffffffffu, Z,  o);
                Tt += __shfl_xor_sync(0xffffffffu, Tt, o);
            }
            if (co == 0 && l < L) { ep->otm[w][row] = m; ep->otz[w][row] = Z; ep->ott[w][row] = Tt; }
        }
    }
    __syncthreads();

    if (tid < BM) {
        int row = tid, l = rowbase + row;
        if (l < L) {
            float s2 = 0.f;
            #pragma unroll 8
            for (int c = 0; c < KDIM; ++c) { float v = x_s[c*BM + row]; s2 += v*v; }
            if (!IS_TOP) s2 += g_e2_top[(size_t)t*NE + ind4s[row]];
            float bv = ep->minv[0][row]; int bi = ep->mini[0][row];
            #pragma unroll
            for (int ww = 1; ww < 8; ++ww) {
                float v = ep->minv[ww][row];
                if (v < bv) { bv = v; bi = ep->mini[ww][row]; }
            }
            ep->ind[row]  = bi;
            ep->dist[row] = s2 + bv;
            if (IS_TOP)
                g_ind4[(size_t)b*L + l] = bi;
            else
                out[ID_OFF + ((size_t)s*B + b)*L + l] = (float)bi;
            if (do_ot) {
                float m = ep->otm[0][row];
                #pragma unroll
                for (int ww = 1; ww < 8; ++ww) m = fmaxf(m, ep->otm[ww][row]);
                float Z = 0.f, Tt = 0.f;
                #pragma unroll
                for (int ww = 0; ww < 8; ++ww) {
                    float sc = expf(ep->otm[ww][row] - m);
                    Z  += ep->otz[ww][row] * sc;
                    Tt += ep->ott[ww][row] * sc;
                }
                float invx = 1.0f / (sqrtf(s2) + EPSF);
                out[OT_OFF + (size_t)b*L + l] = (Z - invx * Tt) / Z;
            }
        }
    }
    __syncthreads();

    if (tid == 0) {
        int nval = L - rowbase; if (nval > BM) nval = BM;
        float sum = 0.f;
        for (int r = 0; r < nval; ++r) sum += ep->dist[r];
        const float div = IS_TOP ? (1.0f / (float)(L * DTOP)) : (1.0f / (float)(L * DLOW));
        atomicAdd(&out[DIFF_OFF], sum * div);
    }

    if (!IS_TOP) {
        const float* embT = g_embT_lvl + (size_t)book * NE * DLOW;
        int nrows = L - rowbase; if (nrows > BM) nrows = BM;
        for (int it = tid; it < nrows*DLOW; it += NTHREADS) {
            int r = it >> 7, c = it & 127;
            out[QUANT_OFF + (((size_t)s*B + b)*L + rowbase + r)*DLOW + c] =
                embT[(size_t)ep->ind[r] * DLOW + c];
        }
    }
}

extern "C" void kernel_launch(void* const* d_in, const int* in_sizes, int n_in,
                              void* d_out, int out_size)
{
    const float* input_list = nullptr;
    const float* cb_top     = nullptr;
    const float* cb_lvl     = nullptr;
    const int*   label      = nullptr;

    for (int i = 0; i < n_in; ++i) {
        switch (in_sizes[i]) {
            case 8028160: input_list = (const float*)d_in[i]; break;
            case 491520:  cb_top     = (const float*)d_in[i]; break;
            case 3932160: cb_lvl     = (const float*)d_in[i]; break;
            case 128:     label      = (const int*)  d_in[i]; break;
        }
    }
    if (!input_list || !cb_top || !cb_lvl || !label) return;

    float* out = (float*)d_out;

    static cudaStream_t s1 = nullptr, s2 = nullptr;
    static cudaEvent_t evRoot = nullptr, ev1 = nullptr, ev2 = nullptr;
    static int attr_set = 0;
    if (!attr_set) {
        cudaFuncSetAttribute(cpre_kernel,
                             cudaFuncAttributeMaxDynamicSharedMemorySize, E_DYN);
        cudaFuncSetAttribute(vq_gemm<true>,
                             cudaFuncAttributeMaxDynamicSharedMemorySize, E_DYN);
        cudaFuncSetAttribute(vq_gemm<false>,
                             cudaFuncAttributeMaxDynamicSharedMemorySize, E_DYN);
        cudaStreamCreateWithFlags(&s1, cudaStreamNonBlocking);
        cudaStreamCreateWithFlags(&s2, cudaStreamNonBlocking);
        cudaEventCreateWithFlags(&evRoot, cudaEventDisableTiming);
        cudaEventCreateWithFlags(&ev1, cudaEventDisableTiming);
        cudaEventCreateWithFlags(&ev2, cudaEventDisableTiming);
        attr_set = 1;
    }

    cudaEventRecord(evRoot, 0);
    cudaStreamWaitEvent(s1, evRoot, 0);
    cudaStreamWaitEvent(s2, evRoot, 0);

    transpose_kernel<<<dim3(NE/32, 4, 60), dim3(32, 8), 0, s1>>>(cb_lvl);
    cudaEventRecord(ev1, s1);

    cpre_kernel<<<dim3(16, 60), NTHREADS, E_DYN, s2>>>(cb_top, cb_lvl);
    cudaEventRecord(ev2, s2);

    norms_kernel<<<NBOOK + 4*NBOOK, NE>>>(cb_top, cb_lvl, out);
    vq_gemm<true><<<dim3(ROWBLOCKS, B), NTHREADS, E_DYN>>>(input_list, cb_top, cb_lvl, label, out);

    cudaStreamWaitEvent(0, ev1, 0);
    cudaStreamWaitEvent(0, ev2, 0);
    vq_gemm<false><<<dim3(ROWBLOCKS, B, 4), NTHREADS, E_DYN>>>(input_list, cb_top, cb_lvl, label, out);
}